// round 3
// baseline (speedup 1.0000x reference)
#include <cuda_runtime.h>

// ContConv1dDenseSim: out[b,l,o] = sum_{j in band, i} feat[b,j,i] * kv(dt_{l,j})[i,o]
// kv = MLP(relu) on scalar dt; banded causal mask (width 30); true_ids column mask;
// row-validity l <= 6*(len-1).
//
// Refactor (exact): FW2[j,h,o] = sum_i feat[j,i]*w2[h,i*16+o]; FB2[j,o] = sum_i feat[j,i]*b2[i*16+o]
// out[l,o] = sum_{j in band} ( FB2[j,o] + sum_h relu(dt*w1_h + b1_h) * FW2[j,h,o] )
// true_ids folded in by zeroing feat rows (reference zeroes the whole kv incl. bias path).
//
// Input robustness: lengths may be int32 or int64; true_ids may be 1-byte bool or int32;
// sim_size scalar slot may or may not exist. All detected at runtime from safe reads.

namespace cc {
constexpr int LEN     = 512;
constexpr int BSZ     = 2;
constexpr int IN_CH   = 16;
constexpr int OUT_CH  = 16;
constexpr int HID     = 8;
constexpr int BAND    = 30;                 // j in [l-29, l]  ((sim_size+1)*kernel_size)
constexpr int TILE_L  = 8;
constexpr int NJMAX   = BAND - 1 + TILE_L;  // 37
constexpr int FW2_STR = HID * OUT_CH + OUT_CH; // 144; 144%32==16 -> conflict-free halves
}

__global__ __launch_bounds__(128, 4)
void cc1d_fused_kernel(const float* __restrict__ times,
                       const float* __restrict__ features,
                       const int* __restrict__ lengths_i32,   // int32 or int64 layout
                       const void* __restrict__ true_ids_raw, // u8 or int32 layout
                       const float* __restrict__ w1,
                       const float* __restrict__ b1,
                       const float* __restrict__ w2,
                       const float* __restrict__ b2,
                       float* __restrict__ out)
{
    using namespace cc;
    __shared__ float feats[NJMAX * IN_CH];
    __shared__ float fw2s[NJMAX * FW2_STR];
    __shared__ float ts[NJMAX];
    __shared__ float w1s[HID], b1s[HID];
    __shared__ int   tid_byte_layout;   // 1 if true_ids is 1-byte elements

    const int b       = blockIdx.y;
    const int l_start = blockIdx.x * TILE_L;
    const int t       = threadIdx.x;

    // ---- true_ids layout detection (first 256 bytes only: safe either way).
    // int32-bool values are 0/1, so any nonzero byte above byte-0 => byte layout.
    if (t < 32) {
        unsigned int w0 = ((const unsigned int*)true_ids_raw)[t];
        unsigned int w1x = ((const unsigned int*)true_ids_raw)[t + 32];
        unsigned int hit = ((w0 | w1x) & 0xFFFFFF00u) ? 1u : 0u;
        unsigned int bal = __ballot_sync(0xFFFFFFFFu, hit);
        if (t == 0) tid_byte_layout = (bal != 0u);
    }

    int j0 = l_start - (BAND - 1); if (j0 < 0) j0 = 0;
    const int j1 = l_start + TILE_L - 1;
    const int nj = j1 - j0 + 1;                // <= NJMAX

    if (t >= 32 && t < 32 + HID) { w1s[t - 32] = w1[t - 32]; b1s[t - 32] = b1[t - 32]; }
    if (t >= 64 && t - 64 < nj)  { ts[t - 64] = times[b * LEN + j0 + (t - 64)]; }
    __syncthreads();   // tid_byte_layout, w1s/b1s, ts visible

    const bool byte_layout = (tid_byte_layout != 0);
    for (int idx = t; idx < nj * IN_CH; idx += 128) {
        const int jr = idx >> 4, i = idx & 15;
        const int j  = j0 + jr;
        bool act;
        if (byte_layout) act = ((const unsigned char*)true_ids_raw)[b * LEN + j] != 0;
        else             act = ((const int*)true_ids_raw)[b * LEN + j] != 0;
        feats[idx] = act ? features[(b * LEN + j) * IN_CH + i] : 0.0f;
    }

    const int h = t >> 4;      // phase1: hidden unit; phase2: l_local
    const int o = t & 15;

    float w2col[IN_CH];
    #pragma unroll
    for (int i = 0; i < IN_CH; i++)
        w2col[i] = w2[h * (IN_CH * OUT_CH) + i * OUT_CH + o];
    float b2col[IN_CH];
    if (h == 0) {
        #pragma unroll
        for (int i = 0; i < IN_CH; i++) b2col[i] = b2[i * OUT_CH + o];
    }
    __syncthreads();

    // ---- phase 1: FW2 / FB2 for the band ----
    for (int jr = 0; jr < nj; jr++) {
        const float* fj = &feats[jr * IN_CH];
        float acc = 0.0f;
        #pragma unroll
        for (int i = 0; i < IN_CH; i++) acc = fmaf(fj[i], w2col[i], acc);
        fw2s[jr * FW2_STR + h * OUT_CH + o] = acc;
        if (h == 0) {
            float ab = 0.0f;
            #pragma unroll
            for (int i = 0; i < IN_CH; i++) ab = fmaf(fj[i], b2col[i], ab);
            fw2s[jr * FW2_STR + HID * OUT_CH + o] = ab;
        }
    }
    __syncthreads();

    // ---- phase 2: band reduction per (l, o) ----
    const int l  = l_start + h;
    const int lr = l - j0;
    const float tl = ts[lr];

    float w1r[HID], b1r[HID];
    #pragma unroll
    for (int k = 0; k < HID; k++) { w1r[k] = w1s[k]; b1r[k] = b1s[k]; }

    int jr_lo = lr - (BAND - 1); if (jr_lo < 0) jr_lo = 0;
    float acc = 0.0f;
    for (int jr = jr_lo; jr <= lr; jr++) {
        const float dt = tl - ts[jr];
        const float* fr = &fw2s[jr * FW2_STR];
        float a = fr[HID * OUT_CH + o];          // FB2 term
        #pragma unroll
        for (int k = 0; k < HID; k++) {
            float hv = fmaf(dt, w1r[k], b1r[k]);
            hv = hv > 0.0f ? hv : 0.0f;
            a = fmaf(hv, fr[k * OUT_CH + o], a);
        }
        acc += a;
    }

    // ---- lengths: int32 vs int64 layout (true lengths >= 1, so hi-word==0 <=> int64) ----
    int len;
    if (lengths_i32[1] == 0) len = lengths_i32[2 * b];  // int64 little-endian
    else                     len = lengths_i32[b];      // int32
    const bool valid = l <= 6 * (len - 1);
    out[(b * LEN + l) * OUT_CH + o] = valid ? acc : 0.0f;
}

extern "C" void kernel_launch(void* const* d_in, const int* in_sizes, int n_in,
                              void* d_out, int out_size) {
    using namespace cc;
    // dict order: times, features, lengths, true_ids, [sim_size], w1, b1, w2, b2
    const float* times    = (const float*)d_in[0];
    const float* features = (const float*)d_in[1];
    const int*   lengths  = (const int*)d_in[2];
    const void*  tids     = d_in[3];

    int base = 4;
    if (n_in >= 9 && in_sizes[4] == 1) base = 5;  // sim_size scalar occupies slot 4

    const float* w1 = (const float*)d_in[base + 0];
    const float* b1 = (const float*)d_in[base + 1];
    const float* w2 = (const float*)d_in[base + 2];
    const float* b2 = (const float*)d_in[base + 3];
    float*       out = (float*)d_out;

    dim3 grid(LEN / TILE_L, BSZ);   // 64 x 2 = 128 blocks
    cc1d_fused_kernel<<<grid, 128>>>(times, features, lengths, tids,
                                     w1, b1, w2, b2, out);
}

// round 4
// speedup vs baseline: 1.2316x; 1.2316x over previous
#include <cuda_runtime.h>

// ContConv1dDenseSim: out[b,l,o] = sum_{j in band, i} feat[b,j,i] * kv(dt_{l,j})[i,o]
// kv = MLP(relu) on scalar dt; banded causal mask (width 30); true_ids column mask;
// row-validity l <= 6*(len-1).
//
// Refactor (exact): FW2[j,h,o] = sum_i feat[j,i]*w2[h,i*16+o]; FB2[j,o] = sum_i feat[j,i]*b2[i*16+o]
// out[l,o] = sum_{j in band} ( FB2[j,o] + sum_h relu(dt*w1_h + b1_h) * FW2[j,h,o] )
//
// R4: latency-bound fix — 512 threads/block, 4-way split of both the phase-1 j-range
// and the phase-2 band, dual accumulators. Grid stays 128 blocks (1/SM, 16 warps/SM).

namespace cc {
constexpr int LEN     = 512;
constexpr int BSZ     = 2;
constexpr int IN_CH   = 16;
constexpr int OUT_CH  = 16;
constexpr int HID     = 8;
constexpr int BAND    = 30;                 // j in [l-29, l]
constexpr int TILE_L  = 8;
constexpr int NJMAX   = BAND - 1 + TILE_L;  // 37
constexpr int FW2_STR = HID * OUT_CH + OUT_CH; // 144; %32==16 -> conflict-free l-halves
constexpr int NTHR    = 512;
}

__global__ __launch_bounds__(512, 1)
void cc1d_fused_kernel(const float* __restrict__ times,
                       const float* __restrict__ features,
                       const int* __restrict__ lengths_i32,   // int32 or int64 layout
                       const void* __restrict__ true_ids_raw, // u8 or int32 layout
                       const float* __restrict__ w1,
                       const float* __restrict__ b1,
                       const float* __restrict__ w2,
                       const float* __restrict__ b2,
                       float* __restrict__ out)
{
    using namespace cc;
    __shared__ float feats[NJMAX * IN_CH];
    __shared__ float fw2s[NJMAX * FW2_STR];
    __shared__ float ts[NJMAX];
    __shared__ float w1s[HID], b1s[HID];
    __shared__ float partial[3 * 128];
    __shared__ int   tid_byte_layout;   // 1 if true_ids is 1-byte elements

    const int b       = blockIdx.y;
    const int l_start = blockIdx.x * TILE_L;
    const int t       = threadIdx.x;
    const int g       = t >> 7;         // work-split group 0..3
    const int m       = t & 127;
    const int h       = m >> 4;         // hidden unit (phase1) / l_local (phase2)
    const int o       = m & 15;

    // ---- true_ids layout detection (first 256 bytes: safe either way).
    // int32-bool values are 0/1, so any nonzero byte above byte-0 => byte layout.
    if (t < 32) {
        unsigned int v0 = ((const unsigned int*)true_ids_raw)[t];
        unsigned int v1 = ((const unsigned int*)true_ids_raw)[t + 32];
        unsigned int hit = ((v0 | v1) & 0xFFFFFF00u) ? 1u : 0u;
        unsigned int bal = __ballot_sync(0xFFFFFFFFu, hit);
        if (t == 0) tid_byte_layout = (bal != 0u);
    }

    int j0 = l_start - (BAND - 1); if (j0 < 0) j0 = 0;
    const int nj = (l_start + TILE_L - 1) - j0 + 1;   // <= NJMAX

    if (t >= 32 && t < 32 + HID) { w1s[t - 32] = w1[t - 32]; b1s[t - 32] = b1[t - 32]; }
    if (t >= 64 && t - 64 < nj)  { ts[t - 64] = times[b * LEN + j0 + (t - 64)]; }
    __syncthreads();   // detection + ts + w1s visible

    const bool byte_layout = (tid_byte_layout != 0);
    for (int idx = t; idx < nj * IN_CH; idx += NTHR) {
        const int jr = idx >> 4, i = idx & 15;
        const int j  = j0 + jr;
        bool act;
        if (byte_layout) act = ((const unsigned char*)true_ids_raw)[b * LEN + j] != 0;
        else             act = ((const int*)true_ids_raw)[b * LEN + j] != 0;
        feats[idx] = act ? features[(b * LEN + j) * IN_CH + i] : 0.0f;
    }

    // per-thread weight column (L2-resident global reads, overlap with feats)
    float w2col[IN_CH];
    #pragma unroll
    for (int i = 0; i < IN_CH; i++)
        w2col[i] = w2[h * (IN_CH * OUT_CH) + i * OUT_CH + o];
    float b2col[IN_CH];
    if (h == 0) {
        #pragma unroll
        for (int i = 0; i < IN_CH; i++) b2col[i] = b2[i * OUT_CH + o];
    }
    __syncthreads();

    // ---- phase 1: FW2 / FB2, j-range split 4 ways across groups ----
    {
        const int q = (nj + 3) >> 2;
        const int jrA = g * q;
        int jrB = jrA + q; if (jrB > nj) jrB = nj;
        for (int jr = jrA; jr < jrB; jr++) {
            const float* fj = &feats[jr * IN_CH];
            float acc = 0.0f;
            #pragma unroll
            for (int i = 0; i < IN_CH; i++) acc = fmaf(fj[i], w2col[i], acc);
            fw2s[jr * FW2_STR + h * OUT_CH + o] = acc;
            if (h == 0) {
                float ab = 0.0f;
                #pragma unroll
                for (int i = 0; i < IN_CH; i++) ab = fmaf(fj[i], b2col[i], ab);
                fw2s[jr * FW2_STR + HID * OUT_CH + o] = ab;
            }
        }
    }
    __syncthreads();

    // ---- phase 2: band reduction per (l, o), band split 4 ways across groups ----
    const int l  = l_start + h;      // h == l_local here
    const int lr = l - j0;
    const float tl = ts[lr];

    float w1r[HID], b1r[HID];
    #pragma unroll
    for (int k = 0; k < HID; k++) { w1r[k] = w1s[k]; b1r[k] = b1s[k]; }

    int jr_lo = lr - (BAND - 1); if (jr_lo < 0) jr_lo = 0;
    const int blen = lr - jr_lo + 1;
    const int q2 = (blen + 3) >> 2;
    const int js = jr_lo + g * q2;
    int je = js + q2; if (je > lr + 1) je = lr + 1;

    float acc0 = 0.0f, acc1 = 0.0f;
    for (int jr = js; jr < je; jr++) {
        const float dt = tl - ts[jr];
        const float* fr = &fw2s[jr * FW2_STR];
        float a0 = fr[HID * OUT_CH + o];   // FB2 term
        float a1 = 0.0f;
        #pragma unroll
        for (int k = 0; k < HID; k += 2) {
            float hv0 = fmaf(dt, w1r[k],     b1r[k]);     hv0 = hv0 > 0.0f ? hv0 : 0.0f;
            float hv1 = fmaf(dt, w1r[k + 1], b1r[k + 1]); hv1 = hv1 > 0.0f ? hv1 : 0.0f;
            a0 = fmaf(hv0, fr[k * OUT_CH + o],       a0);
            a1 = fmaf(hv1, fr[(k + 1) * OUT_CH + o], a1);
        }
        acc0 += a0; acc1 += a1;
    }
    float acc = acc0 + acc1;

    if (g > 0) partial[(g - 1) * 128 + m] = acc;
    __syncthreads();

    if (g == 0) {
        acc += partial[m] + partial[128 + m] + partial[256 + m];
        int len;
        if (lengths_i32[1] == 0) len = lengths_i32[2 * b];  // int64 little-endian
        else                     len = lengths_i32[b];      // int32
        const bool valid = l <= 6 * (len - 1);
        out[(b * LEN + l) * OUT_CH + o] = valid ? acc : 0.0f;
    }
}

extern "C" void kernel_launch(void* const* d_in, const int* in_sizes, int n_in,
                              void* d_out, int out_size) {
    using namespace cc;
    // dict order: times, features, lengths, true_ids, [sim_size], w1, b1, w2, b2
    const float* times    = (const float*)d_in[0];
    const float* features = (const float*)d_in[1];
    const int*   lengths  = (const int*)d_in[2];
    const void*  tids     = d_in[3];

    int base = 4;
    if (n_in >= 9 && in_sizes[4] == 1) base = 5;  // sim_size scalar occupies slot 4

    const float* w1 = (const float*)d_in[base + 0];
    const float* b1 = (const float*)d_in[base + 1];
    const float* w2 = (const float*)d_in[base + 2];
    const float* b2 = (const float*)d_in[base + 3];
    float*       out = (float*)d_out;

    dim3 grid(LEN / TILE_L, BSZ);   // 64 x 2 = 128 blocks, 1 per SM
    cc1d_fused_kernel<<<grid, NTHR>>>(times, features, lengths, tids,
                                      w1, b1, w2, b2, out);
}